// round 16
// baseline (speedup 1.0000x reference)
#include <cuda_runtime.h>
#include <cuda_fp16.h>
#include <cstdint>

typedef unsigned long long ull;

#define BB 4
#define HH 224
#define WL 224
#define HW 50176
#define NC 64
#define EE 768
#define SS 256

// ---- scratch ----
__device__ __half g_h1[BB*HW*64];    // conv1 output, PIXEL-MAJOR fp16 [b][pix][ci]
__device__ __half g_h2[BB*HW*64];    // conv2 output, PIXEL-MAJOR fp16 [b][pix][ci]
__device__ int   g_cnt[BB*SS];
__device__ int   g_off[BB*SS];
__device__ int   g_cur[BB*SS];
__device__ int   g_order[BB*HW];

// ---- packed fp32x2 helpers ----
__device__ __forceinline__ ull pack2(float a, float b){
    ull d; asm("mov.b64 %0,{%1,%2};" : "=l"(d) : "f"(a), "f"(b)); return d;
}
__device__ __forceinline__ void ffma2(ull& d, ull a, ull b){
    asm("fma.rn.f32x2 %0,%1,%2,%0;" : "+l"(d) : "l"(a), "l"(b));
}
__device__ __forceinline__ float2 unpack2(ull d){
    float2 f; asm("mov.b64 {%0,%1},%2;" : "=f"(f.x), "=f"(f.y) : "l"(d)); return f;
}

__device__ __forceinline__ uint32_t smem_u32(const void* p){
    uint32_t a;
    asm("{ .reg .u64 t; cvta.to.shared.u64 t, %1; cvt.u32.u64 %0, t; }" : "=r"(a) : "l"(p));
    return a;
}
__device__ __forceinline__ uint32_t sw128(uint32_t off){ return off ^ ((off >> 3) & 0x70); }

// ---- cp.async (LDGSTS) helpers ----
__device__ __forceinline__ void cp_async16(uint32_t dst, const void* src, bool valid){
    int sz = valid ? 16 : 0;
    asm volatile("cp.async.cg.shared.global [%0], [%1], 16, %2;"
                 :: "r"(dst), "l"(src), "r"(sz));
}
#define CP_COMMIT() asm volatile("cp.async.commit_group;" ::: "memory")
#define CP_WAIT(n)  asm volatile("cp.async.wait_group %0;" :: "n"(n) : "memory")

// ---- mma.sync fp16 helpers ----
__device__ __forceinline__ void ldsm_x4(uint32_t* r, uint32_t a){
    asm volatile("ldmatrix.sync.aligned.m8n8.x4.shared.b16 {%0,%1,%2,%3}, [%4];"
        : "=r"(r[0]),"=r"(r[1]),"=r"(r[2]),"=r"(r[3]) : "r"(a));
}
__device__ __forceinline__ void mma_fp16(float* d, const uint32_t* a, const uint32_t* b){
    asm volatile("mma.sync.aligned.m16n8k16.row.col.f32.f16.f16.f32 "
        "{%0,%1,%2,%3}, {%4,%5,%6,%7}, {%8,%9}, {%0,%1,%2,%3};"
        : "+f"(d[0]),"+f"(d[1]),"+f"(d[2]),"+f"(d[3])
        : "r"(a[0]),"r"(a[1]),"r"(a[2]),"r"(a[3]), "r"(b[0]),"r"(b[1]));
}

// ================= zero counters ============================================
__global__ void k_zero(){
    int t = threadIdx.x;
    g_cnt[t] = 0; g_cur[t] = 0;
}

// ================= conv1: 3->64 3x3 relu, f32x2 packed, fp16 pixel-major ====
__global__ __launch_bounds__(256) void k_conv1(const float* __restrict__ img,
                                               const float* __restrict__ w1){
    __shared__ ull ws[32*28];
    int tid = threadIdx.x;
    for (int i = tid; i < 32*28; i += 256){
        int cp = i / 28, t = i % 28;
        ws[i] = (t < 27) ? pack2(w1[(2*cp)*27+t], w1[(2*cp+1)*27+t]) : 0ULL;
    }
    __syncthreads();
    int b = blockIdx.y;
    int p = blockIdx.x*256 + tid;
    int y = p / WL, x = p % WL;
    ull vp[28];
#pragma unroll
    for (int ci = 0; ci < 3; ci++)
#pragma unroll
    for (int ky = 0; ky < 3; ky++)
#pragma unroll
    for (int kx = 0; kx < 3; kx++){
        int yy = y + ky - 1, xx = x + kx - 1;
        float val = 0.f;
        if (yy >= 0 && yy < HH && xx >= 0 && xx < WL)
            val = img[(size_t)(b*3+ci)*HW + yy*WL + xx];
        vp[ci*9 + ky*3 + kx] = pack2(val, val);
    }
    vp[27] = 0ULL;
    uint32_t pk[32];
#pragma unroll 2
    for (int cp = 0; cp < 32; cp++){
        ull acc = 0ULL;
        const ulonglong2* wp = (const ulonglong2*)&ws[cp*28];
#pragma unroll
        for (int tp = 0; tp < 14; tp++){
            ulonglong2 w = wp[tp];
            ffma2(acc, vp[2*tp],   w.x);
            ffma2(acc, vp[2*tp+1], w.y);
        }
        float2 r = unpack2(acc);
        __half2 h = __floats2half2_rn(fmaxf(r.x,0.f), fmaxf(r.y,0.f));
        pk[cp] = *(uint32_t*)&h;
    }
    uint4* dst = (uint4*)(g_h1 + ((size_t)b*HW + p)*64);
#pragma unroll
    for (int j = 0; j < 8; j++)
        dst[j] = make_uint4(pk[4*j], pk[4*j+1], pk[4*j+2], pk[4*j+3]);
}

// ================= conv2: per-batch-pair, persistent + cp.async =============
// Takes batch0 (0 or 2): processes 196 tiles of 2 batches. Grid 148.
#define C2_WS 0
#define C2_F0 73728
#define C2_F1 152064
#define C2_SMEM 230400
#define C2_TILES 196
#define C2_GRID 148

__device__ __forceinline__ void c2_stage(uint32_t sb, uint32_t foff, int batch0,
                                         int tt, int tid){
    int b  = batch0 + tt / 98;
    int rem = tt % 98;
    int y0 = (rem / 7) * 16;
    int x0 = (rem - (rem/7)*7) * 32;
    const __half* src = g_h1 + (size_t)b*HW*64;
    for (int lin = tid; lin < 612*8; lin += 256){
        int slot = lin >> 3, part = lin & 7;
        int gy = y0 + slot/34 - 1, gx = x0 + (slot%34) - 1;
        bool v = (gy >= 0 && gy < HH && gx >= 0 && gx < WL);
        const void* s = v ? (const void*)(src + ((size_t)gy*WL + gx)*64 + part*8)
                          : (const void*)src;
        cp_async16(sb + foff + sw128((uint32_t)(slot*128 + part*16)), s, v);
    }
}

__device__ __forceinline__ void c2_compute(uint32_t sb, uint32_t foff, int batch0,
                                           int tt, int wid, int lane){
    int b  = batch0 + tt / 98;
    int rem = tt % 98;
    int y0 = (rem / 7) * 16;
    int x0 = (rem - (rem/7)*7) * 32;
    __half* dsth = g_h2 + (size_t)b*HW*64;

    int rowA = lane & 15, chA = lane >> 4;
    int rowB8 = lane & 7, chB = (lane>>3)&1, grpB = lane>>4;

    float acc[2][2][8][4];
#pragma unroll
    for (int h = 0; h < 2; h++)
#pragma unroll
    for (int mx = 0; mx < 2; mx++)
#pragma unroll
    for (int nt = 0; nt < 8; nt++)
#pragma unroll
    for (int q = 0; q < 4; q++) acc[h][mx][nt][q] = 0.f;

#pragma unroll 1
    for (int pass = 0; pass < 9; pass++){
        int ky = pass / 3, kx = pass - ky*3;
        uint32_t wbase = sb + C2_WS + pass*8192;
#pragma unroll
        for (int kt = 0; kt < 4; kt++){
            uint32_t bf[8][2];
#pragma unroll
            for (int ntp = 0; ntp < 4; ntp++){
                uint32_t r[4];
                uint32_t a = wbase + sw128((uint32_t)(((ntp*2 + grpB)*8 + rowB8)*128 + kt*32 + chB*16));
                ldsm_x4(r, a);
                bf[2*ntp][0]   = r[0]; bf[2*ntp][1]   = r[1];
                bf[2*ntp+1][0] = r[2]; bf[2*ntp+1][1] = r[3];
            }
#pragma unroll
            for (int half = 0; half < 2; half++){
                int ty = half*8 + wid;
#pragma unroll
                for (int mx = 0; mx < 2; mx++){
                    int slot = (ty + ky)*34 + mx*16 + rowA + kx;
                    uint32_t af[4];
                    ldsm_x4(af, sb + foff + sw128((uint32_t)(slot*128 + kt*32 + chA*16)));
#pragma unroll
                    for (int nt = 0; nt < 8; nt++)
                        mma_fp16(acc[half][mx][nt], af, bf[nt]);
                }
            }
        }
    }

#pragma unroll
    for (int half = 0; half < 2; half++){
        int gy = y0 + half*8 + wid;
#pragma unroll
        for (int mx = 0; mx < 2; mx++){
            int px = x0 + mx*16 + (lane>>2);
            size_t base0 = ((size_t)gy*WL + px)*64;
            size_t base1 = ((size_t)gy*WL + px + 8)*64;
#pragma unroll
            for (int nt = 0; nt < 8; nt++){
                int co = nt*8 + (lane&3)*2;
                __half2 u0 = __floats2half2_rn(fmaxf(acc[half][mx][nt][0],0.f), fmaxf(acc[half][mx][nt][1],0.f));
                __half2 u1 = __floats2half2_rn(fmaxf(acc[half][mx][nt][2],0.f), fmaxf(acc[half][mx][nt][3],0.f));
                *(uint32_t*)(dsth + base0 + co) = *(uint32_t*)&u0;
                *(uint32_t*)(dsth + base1 + co) = *(uint32_t*)&u1;
            }
        }
    }
}

__global__ __launch_bounds__(256) void k_conv2(const float* __restrict__ w2,
                                               int batch0){
    extern __shared__ __align__(1024) char sm[];
    uint32_t sb = smem_u32(sm);
    int tid = threadIdx.x, wid = tid>>5, lane = tid&31;

    for (int lin = tid; lin < 64*64*9; lin += 256){
        float v = w2[lin];
        int co = lin / 576;
        int rem = lin - co*576;
        int ci = rem / 9;
        int k  = rem - ci*9;
        __half hv = __float2half_rn(v);
        *(__half*)(sm + C2_WS + k*8192 + sw128((uint32_t)(co*128 + ci*2))) = hv;
    }

    int n = 0;
    int tiles[2];
    for (int tt = blockIdx.x; tt < C2_TILES; tt += C2_GRID) tiles[n++] = tt;
    if (n == 0) return;

    const uint32_t foff[2] = {C2_F0, C2_F1};

    c2_stage(sb, foff[0], batch0, tiles[0], tid);
    CP_COMMIT();

    for (int k = 0; k < n; k++){
        if (k + 1 < n){
            c2_stage(sb, foff[(k+1)&1], batch0, tiles[k+1], tid);
            CP_COMMIT();
            CP_WAIT(1);
        } else {
            CP_WAIT(0);
        }
        __syncthreads();
        c2_compute(sb, foff[k&1], batch0, tiles[k], wid, lane);
        __syncthreads();
    }
}

// ================= segment counting sort ====================================
__global__ __launch_bounds__(256) void k_hist(const int* __restrict__ seg){
    __shared__ int hist[SS];
    int tid = threadIdx.x;
    hist[tid] = 0;
    __syncthreads();
    int b = blockIdx.y;
    int base = blockIdx.x * 1024;
#pragma unroll
    for (int i = 0; i < 4; i++){
        int s = seg[(size_t)b*HW + base + i*256 + tid];
        atomicAdd(&hist[s], 1);
    }
    __syncthreads();
    atomicAdd(&g_cnt[b*SS + tid], hist[tid]);
}

__global__ void k_scan(){
    __shared__ int s[1024];
    int t = threadIdx.x;
    int v = g_cnt[t];
    s[t] = v;
    __syncthreads();
    for (int d = 1; d < 1024; d <<= 1){
        int add = (t >= d) ? s[t-d] : 0;
        __syncthreads();
        s[t] += add;
        __syncthreads();
    }
    g_off[t] = s[t] - v;
}

__global__ __launch_bounds__(256) void k_scatter(const int* __restrict__ seg){
    int b = blockIdx.y;
    int p = blockIdx.x*256 + threadIdx.x;
    int sgm = seg[(size_t)b*HW + p];
    int bin = b*SS + sgm;
    int idx = atomicAdd(&g_cur[bin], 1);
    g_order[g_off[bin] + idx] = p;
}

// ================= conv3+pool: per-batch-pair, af-resident, pipelined =======
// Takes batch0: processes 512 bins [batch0*256, batch0*256+512). Grid 148.
#define W_OFF 0
#define F3_0  98304
#define F3_1  131072
#define C3_SMEM 163840
#define C3_GRID 148
#define C3_TPX 256

__device__ __forceinline__ void c3_stage(uint32_t sb, uint32_t foff,
                                         const __half* featb, int off,
                                         int tbase, int npix, int nrows, int tid){
    for (int lin = tid; lin < nrows*8; lin += 256){
        int r = lin >> 3, part = lin & 7;
        int idx = tbase + r;
        bool v = idx < npix;
        const void* s;
        if (v){
            int pix = g_order[off + idx];
            s = (const void*)(featb + (size_t)pix*64 + part*8);
        } else s = (const void*)featb;
        cp_async16(sb + foff + sw128((uint32_t)(r*128 + part*16)), s, v);
    }
}

__global__ __launch_bounds__(256, 1) void k_conv3pool(const float* __restrict__ w3,
                                                      float* __restrict__ out,
                                                      int batch0){
    extern __shared__ __align__(1024) char sm[];
    int tid  = threadIdx.x;
    int wid  = tid >> 5;
    int lane = tid & 31;
    uint32_t sbase = smem_u32(sm);

    // ---- stage W once ----
#pragma unroll
    for (int rr = 0; rr < 3; rr++){
        int e = tid + rr*256;
        const float4* wrow = (const float4*)(w3 + (size_t)e*64);
#pragma unroll
        for (int k = 0; k < 16; k++){
            float4 f4 = wrow[k];
            __half2 h0 = __float22half2_rn(make_float2(f4.x, f4.y));
            __half2 h1 = __float22half2_rn(make_float2(f4.z, f4.w));
            uint2 u; u.x = *(uint32_t*)&h0; u.y = *(uint32_t*)&h1;
            *(uint2*)(sm + W_OFF + sw128((uint32_t)(e*128 + k*8))) = u;
        }
    }
    __syncthreads();

    // ---- weight fragments resident in registers ----
    int rowA = lane & 15, chA = lane >> 4;
    uint32_t af[6][4][4];
#pragma unroll
    for (int i = 0; i < 6; i++){
        int e0 = (wid*6 + i)*16;
#pragma unroll
        for (int kt = 0; kt < 4; kt++)
            ldsm_x4(af[i][kt], sbase + W_OFF + sw128((uint32_t)((e0 + rowA)*128 + kt*32 + chA*16)));
    }

    int rowB = lane & 7, chB = (lane >> 3) & 1, grpB = lane >> 4;
    const uint32_t foff[2] = {F3_0, F3_1};

    int base = batch0*SS, lim = base + 2*SS;
    int mybins[4]; int nb = 0;
    for (int bin = base + blockIdx.x; bin < lim; bin += C3_GRID) mybins[nb++] = bin;
    if (nb == 0) return;

    // prologue: stage tile 0 of bin 0
    {
        int bin = mybins[0];
        int npix = g_cnt[bin], off = g_off[bin];
        const __half* fb = g_h2 + (size_t)(bin >> 8)*HW*64;
        int rem0 = npix > C3_TPX ? C3_TPX : (npix < 0 ? 0 : npix);
        int nr0 = ((rem0 + 31) >> 5) * 32;
        c3_stage(sbase, foff[0], fb, off, 0, npix, nr0, tid);
    }
    CP_COMMIT();
    int pbuf = 0;

#pragma unroll 1
    for (int bi = 0; bi < nb; bi++){
        int bin  = mybins[bi];
        int npix = g_cnt[bin];
        int off  = g_off[bin];
        int ntiles = (npix + C3_TPX-1) / C3_TPX; if (ntiles < 1) ntiles = 1;

        float acc[6][2];
#pragma unroll
        for (int i = 0; i < 6; i++){ acc[i][0] = 0.f; acc[i][1] = 0.f; }

        for (int t = 0; t < ntiles; t++){
            int rem = npix - t*C3_TPX;
            if (rem > C3_TPX) rem = C3_TPX;
            if (rem < 0) rem = 0;
            int ntcN = (rem + 31) >> 5;

            bool has_next = false; int nbin = 0, ntb = 0;
            if (t + 1 < ntiles){ nbin = bin; ntb = t + 1; has_next = true; }
            else if (bi + 1 < nb){ nbin = mybins[bi+1]; ntb = 0; has_next = true; }
            if (has_next){
                int nnp = g_cnt[nbin], noff = g_off[nbin];
                const __half* nfb = g_h2 + (size_t)(nbin >> 8)*HW*64;
                int nrem = nnp - ntb*C3_TPX;
                if (nrem > C3_TPX) nrem = C3_TPX;
                if (nrem < 0) nrem = 0;
                int nr = ((nrem + 31) >> 5) * 32;
                c3_stage(sbase, foff[pbuf^1], nfb, noff, ntb*C3_TPX, nnp, nr, tid);
                CP_COMMIT();
                CP_WAIT(1);
            } else {
                CP_WAIT(0);
            }
            __syncthreads();
            uint32_t fbp = sbase + foff[pbuf];

#pragma unroll 1
            for (int ntc = 0; ntc < ntcN; ntc++){
                uint32_t bf[4][4][2];
#pragma unroll
                for (int kt = 0; kt < 4; kt++)
#pragma unroll
                for (int jp = 0; jp < 2; jp++){
                    uint32_t r[4];
                    int px = (ntc*4 + jp*2 + grpB)*8 + rowB;
                    ldsm_x4(r, fbp + sw128((uint32_t)(px*128 + kt*32 + chB*16)));
                    bf[jp*2][kt][0]   = r[0]; bf[jp*2][kt][1]   = r[1];
                    bf[jp*2+1][kt][0] = r[2]; bf[jp*2+1][kt][1] = r[3];
                }
#pragma unroll
                for (int i = 0; i < 6; i++){
                    float d[4][4];
#pragma unroll
                    for (int j = 0; j < 4; j++)
#pragma unroll
                    for (int q = 0; q < 4; q++) d[j][q] = 0.f;
#pragma unroll
                    for (int kt = 0; kt < 4; kt++)
#pragma unroll
                    for (int j = 0; j < 4; j++)
                        mma_fp16(d[j], af[i][kt], bf[j][kt]);
#pragma unroll
                    for (int j = 0; j < 4; j++){
                        acc[i][0] += fmaxf(d[j][0], 0.f) + fmaxf(d[j][1], 0.f);
                        acc[i][1] += fmaxf(d[j][2], 0.f) + fmaxf(d[j][3], 0.f);
                    }
                }
            }
            __syncthreads();
            pbuf ^= 1;
        }

        float inv = 1.f / (float)max(npix, 1);
#pragma unroll
        for (int i = 0; i < 6; i++){
            acc[i][0] += __shfl_xor_sync(0xffffffffu, acc[i][0], 1);
            acc[i][0] += __shfl_xor_sync(0xffffffffu, acc[i][0], 2);
            acc[i][1] += __shfl_xor_sync(0xffffffffu, acc[i][1], 1);
            acc[i][1] += __shfl_xor_sync(0xffffffffu, acc[i][1], 2);
        }
        if ((lane & 3) == 0){
            int row = lane >> 2;
            float* ob = out + (size_t)bin*EE;
#pragma unroll
            for (int i = 0; i < 6; i++){
                int e = (wid*6 + i)*16 + row;
                ob[e]     = acc[i][0] * inv;
                ob[e + 8] = acc[i][1] * inv;
            }
        }
    }
}

// ================= positional MLP: 128 CTAs =================================
#define POS_ROWS 32
__global__ __launch_bounds__(192) void k_pos(const float* __restrict__ cent,
        const float* __restrict__ w1, const float* __restrict__ b1,
        const float* __restrict__ w2, const float* __restrict__ b2,
        float* __restrict__ out){
    __shared__ __align__(16) float h2[384*POS_ROWS];
    int tid = threadIdx.x;
    int eq  = blockIdx.x;
    int rb  = blockIdx.y * POS_ROWS;
    for (int lin = tid; lin < 384*POS_ROWS; lin += 192){
        int j = lin >> 5, r = lin & 31;
        int rid = rb + r;
        float c0 = cent[rid*2+0] * (1.f/223.f);
        float c1 = cent[rid*2+1] * (1.f/223.f);
        h2[j*POS_ROWS + r] = fmaxf(fmaf(c0, w1[j], fmaf(c1, w1[384+j], b1[j])), 0.f);
    }
    __syncthreads();
    int e = eq*192 + tid;
    ull acc[16];
#pragma unroll
    for (int q = 0; q < 16; q++) acc[q] = 0ULL;
    for (int j = 0; j < 384; j++){
        float wv = w2[(size_t)j*768 + e];
        ull wp = pack2(wv, wv);
        const ull* hp = (const ull*)&h2[j*POS_ROWS];
#pragma unroll
        for (int q = 0; q < 16; q++) ffma2(acc[q], hp[q], wp);
    }
    float bv = b2[e];
#pragma unroll
    for (int q = 0; q < 16; q++){
        float2 v = unpack2(acc[q]);
        int rid = rb + 2*q;
        out[(size_t)rid*768 + e]     = v.x + bv;
        out[(size_t)(rid+1)*768 + e] = v.y + bv;
    }
}

// ================= launcher: 3-stream batch-pipelined fork/join =============
extern "C" void kernel_launch(void* const* d_in, const int* in_sizes, int n_in,
                              void* d_out, int out_size){
    const float* img  = (const float*)d_in[0];
    const int*   seg  = (const int*)d_in[1];
    const float* cent = (const float*)d_in[2];
    const float* w1   = (const float*)d_in[3];
    const float* w2   = (const float*)d_in[4];
    const float* w3   = (const float*)d_in[5];
    const float* pw1  = (const float*)d_in[6];
    const float* pb1  = (const float*)d_in[7];
    const float* pw2  = (const float*)d_in[8];
    const float* pb2  = (const float*)d_in[9];
    float* out = (float*)d_out;

    static cudaStream_t sB = nullptr, sC = nullptr;
    static cudaEvent_t  e0 = nullptr, e1 = nullptr, E2a = nullptr, eC = nullptr;
    if (!sB){
        cudaStreamCreateWithFlags(&sB, cudaStreamNonBlocking);
        cudaStreamCreateWithFlags(&sC, cudaStreamNonBlocking);
        cudaEventCreateWithFlags(&e0,  cudaEventDisableTiming);
        cudaEventCreateWithFlags(&e1,  cudaEventDisableTiming);
        cudaEventCreateWithFlags(&E2a, cudaEventDisableTiming);
        cudaEventCreateWithFlags(&eC,  cudaEventDisableTiming);
    }

    cudaFuncSetAttribute(k_conv2,
                         cudaFuncAttributeMaxDynamicSharedMemorySize, C2_SMEM);
    cudaFuncSetAttribute(k_conv3pool,
                         cudaFuncAttributeMaxDynamicSharedMemorySize, C3_SMEM);

    // fork
    cudaEventRecord(e0, 0);
    cudaStreamWaitEvent(sB, e0, 0);
    cudaStreamWaitEvent(sC, e0, 0);

    // stream B: sort chain + pos (independent of conv)
    k_zero<<<1, 1024, 0, sB>>>();
    k_hist<<<dim3(49,4), 256, 0, sB>>>(seg);
    k_scan<<<1, 1024, 0, sB>>>();
    k_scatter<<<dim3(196,4), 256, 0, sB>>>(seg);
    k_pos<<<dim3(4,32), 192, 0, sB>>>(cent, pw1, pb1, pw2, pb2, out + (size_t)BB*SS*EE);
    cudaEventRecord(e1, sB);

    // stream 0: conv1 -> conv2(b0,1) -> conv2(b2,3) -> conv3pool(b2,3)
    k_conv1<<<dim3(196,4), 256>>>(img, w1);
    k_conv2<<<C2_GRID, 256, C2_SMEM>>>(w2, 0);
    cudaEventRecord(E2a, 0);
    k_conv2<<<C2_GRID, 256, C2_SMEM>>>(w2, 2);

    // stream C: conv3pool(b0,1) overlaps conv2(b2,3)
    cudaStreamWaitEvent(sC, E2a, 0);
    cudaStreamWaitEvent(sC, e1, 0);
    k_conv3pool<<<C3_GRID, 256, C3_SMEM, sC>>>(w3, out, 0);
    cudaEventRecord(eC, sC);

    // stream 0 tail: conv3pool(b2,3) after conv2(b2,3) + sort; join with sC
    cudaStreamWaitEvent(0, e1, 0);
    k_conv3pool<<<C3_GRID, 256, C3_SMEM>>>(w3, out, 2);
    cudaStreamWaitEvent(0, eC, 0);
}

// round 17
// speedup vs baseline: 1.1262x; 1.1262x over previous
#include <cuda_runtime.h>
#include <cuda_fp16.h>
#include <cstdint>

typedef unsigned long long ull;

#define BB 4
#define HH 224
#define WL 224
#define HW 50176
#define NC 64
#define EE 768
#define SS 256

// ---- scratch ----
__device__ __half g_h1[BB*HW*64];    // conv1 output, PIXEL-MAJOR fp16 [b][pix][ci]
__device__ __half g_h2[BB*HW*64];    // conv2 output, PIXEL-MAJOR fp16 [b][pix][ci]
__device__ int   g_cnt[BB*SS];
__device__ int   g_off[BB*SS];
__device__ int   g_cur[BB*SS];
__device__ int   g_order[BB*HW];

// ---- packed fp32x2 helpers ----
__device__ __forceinline__ ull pack2(float a, float b){
    ull d; asm("mov.b64 %0,{%1,%2};" : "=l"(d) : "f"(a), "f"(b)); return d;
}
__device__ __forceinline__ void ffma2(ull& d, ull a, ull b){
    asm("fma.rn.f32x2 %0,%1,%2,%0;" : "+l"(d) : "l"(a), "l"(b));
}
__device__ __forceinline__ float2 unpack2(ull d){
    float2 f; asm("mov.b64 {%0,%1},%2;" : "=f"(f.x), "=f"(f.y) : "l"(d)); return f;
}

__device__ __forceinline__ uint32_t smem_u32(const void* p){
    uint32_t a;
    asm("{ .reg .u64 t; cvta.to.shared.u64 t, %1; cvt.u32.u64 %0, t; }" : "=r"(a) : "l"(p));
    return a;
}
__device__ __forceinline__ uint32_t sw128(uint32_t off){ return off ^ ((off >> 3) & 0x70); }

// ---- cp.async (LDGSTS) helpers ----
__device__ __forceinline__ void cp_async16(uint32_t dst, const void* src, bool valid){
    int sz = valid ? 16 : 0;
    asm volatile("cp.async.cg.shared.global [%0], [%1], 16, %2;"
                 :: "r"(dst), "l"(src), "r"(sz));
}
#define CP_COMMIT() asm volatile("cp.async.commit_group;" ::: "memory")
#define CP_WAIT(n)  asm volatile("cp.async.wait_group %0;" :: "n"(n) : "memory")

// ---- mma.sync fp16 helpers ----
__device__ __forceinline__ void ldsm_x4(uint32_t* r, uint32_t a){
    asm volatile("ldmatrix.sync.aligned.m8n8.x4.shared.b16 {%0,%1,%2,%3}, [%4];"
        : "=r"(r[0]),"=r"(r[1]),"=r"(r[2]),"=r"(r[3]) : "r"(a));
}
__device__ __forceinline__ void mma_fp16(float* d, const uint32_t* a, const uint32_t* b){
    asm volatile("mma.sync.aligned.m16n8k16.row.col.f32.f16.f16.f32 "
        "{%0,%1,%2,%3}, {%4,%5,%6,%7}, {%8,%9}, {%0,%1,%2,%3};"
        : "+f"(d[0]),"+f"(d[1]),"+f"(d[2]),"+f"(d[3])
        : "r"(a[0]),"r"(a[1]),"r"(a[2]),"r"(a[3]), "r"(b[0]),"r"(b[1]));
}

// ================= zero counters ============================================
__global__ void k_zero(){
    int t = threadIdx.x;
    g_cnt[t] = 0; g_cur[t] = 0;
}

// ================= conv1: 3->64 3x3 relu, f32x2 packed, fp16 pixel-major ====
__global__ __launch_bounds__(256) void k_conv1(const float* __restrict__ img,
                                               const float* __restrict__ w1){
    __shared__ ull ws[32*28];
    int tid = threadIdx.x;
    for (int i = tid; i < 32*28; i += 256){
        int cp = i / 28, t = i % 28;
        ws[i] = (t < 27) ? pack2(w1[(2*cp)*27+t], w1[(2*cp+1)*27+t]) : 0ULL;
    }
    __syncthreads();
    int b = blockIdx.y;
    int p = blockIdx.x*256 + tid;
    int y = p / WL, x = p % WL;
    ull vp[28];
#pragma unroll
    for (int ci = 0; ci < 3; ci++)
#pragma unroll
    for (int ky = 0; ky < 3; ky++)
#pragma unroll
    for (int kx = 0; kx < 3; kx++){
        int yy = y + ky - 1, xx = x + kx - 1;
        float val = 0.f;
        if (yy >= 0 && yy < HH && xx >= 0 && xx < WL)
            val = img[(size_t)(b*3+ci)*HW + yy*WL + xx];
        vp[ci*9 + ky*3 + kx] = pack2(val, val);
    }
    vp[27] = 0ULL;
    uint32_t pk[32];
#pragma unroll 2
    for (int cp = 0; cp < 32; cp++){
        ull acc = 0ULL;
        const ulonglong2* wp = (const ulonglong2*)&ws[cp*28];
#pragma unroll
        for (int tp = 0; tp < 14; tp++){
            ulonglong2 w = wp[tp];
            ffma2(acc, vp[2*tp],   w.x);
            ffma2(acc, vp[2*tp+1], w.y);
        }
        float2 r = unpack2(acc);
        __half2 h = __floats2half2_rn(fmaxf(r.x,0.f), fmaxf(r.y,0.f));
        pk[cp] = *(uint32_t*)&h;
    }
    uint4* dst = (uint4*)(g_h1 + ((size_t)b*HW + p)*64);
#pragma unroll
    for (int j = 0; j < 8; j++)
        dst[j] = make_uint4(pk[4*j], pk[4*j+1], pk[4*j+2], pk[4*j+3]);
}

// ================= conv2: 512 threads / 16 warps (latency-hiding) ===========
// Warp = (ty-row, nt-half): tyw = wid>>1 (0..7), nthalf = wid&1 owns nt
// [nthalf*4, nthalf*4+4). Per-warp acc[2][2][4][4] = 64 regs. Total LDSM
// unchanged vs 8-warp version (bf halves, af duplicates) -- pure 2x warp
// occupancy experiment. Per-element accumulation order identical.
#define C2_WS 0
#define C2_F0 73728
#define C2_F1 152064
#define C2_SMEM 230400
#define C2_TILES 392
#define C2_GRID 148
#define C2_THR 512

__device__ __forceinline__ void c2_stage(uint32_t sb, uint32_t foff, int tt, int tid){
    int b  = tt / 98;
    int rem = tt - b*98;
    int y0 = (rem / 7) * 16;
    int x0 = (rem - (rem/7)*7) * 32;
    const __half* src = g_h1 + (size_t)b*HW*64;
    for (int lin = tid; lin < 612*8; lin += C2_THR){
        int slot = lin >> 3, part = lin & 7;
        int gy = y0 + slot/34 - 1, gx = x0 + (slot%34) - 1;
        bool v = (gy >= 0 && gy < HH && gx >= 0 && gx < WL);
        const void* s = v ? (const void*)(src + ((size_t)gy*WL + gx)*64 + part*8)
                          : (const void*)src;
        cp_async16(sb + foff + sw128((uint32_t)(slot*128 + part*16)), s, v);
    }
}

__device__ __forceinline__ void c2_compute(uint32_t sb, uint32_t foff, int tt,
                                           int wid, int lane){
    int b  = tt / 98;
    int rem = tt - b*98;
    int y0 = (rem / 7) * 16;
    int x0 = (rem - (rem/7)*7) * 32;
    __half* dsth = g_h2 + (size_t)b*HW*64;

    int tyw    = wid >> 1;     // 0..7
    int nthalf = wid & 1;      // 0..1: nt in [nthalf*4, nthalf*4+4)
    int rowA = lane & 15, chA = lane >> 4;
    int rowB8 = lane & 7, chB = (lane>>3)&1, grpB = lane>>4;

    float acc[2][2][4][4];     // [half][mx][ntl][q]
#pragma unroll
    for (int h = 0; h < 2; h++)
#pragma unroll
    for (int mx = 0; mx < 2; mx++)
#pragma unroll
    for (int nt = 0; nt < 4; nt++)
#pragma unroll
    for (int q = 0; q < 4; q++) acc[h][mx][nt][q] = 0.f;

#pragma unroll 1
    for (int pass = 0; pass < 9; pass++){
        int ky = pass / 3, kx = pass - ky*3;
        uint32_t wbase = sb + C2_WS + pass*8192;
#pragma unroll
        for (int kt = 0; kt < 4; kt++){
            uint32_t bf[4][2];
#pragma unroll
            for (int ntp = 0; ntp < 2; ntp++){
                int ntpg = nthalf*2 + ntp;
                uint32_t r[4];
                uint32_t a = wbase + sw128((uint32_t)(((ntpg*2 + grpB)*8 + rowB8)*128 + kt*32 + chB*16));
                ldsm_x4(r, a);
                bf[2*ntp][0]   = r[0]; bf[2*ntp][1]   = r[1];
                bf[2*ntp+1][0] = r[2]; bf[2*ntp+1][1] = r[3];
            }
#pragma unroll
            for (int half = 0; half < 2; half++){
                int ty = half*8 + tyw;
#pragma unroll
                for (int mx = 0; mx < 2; mx++){
                    int slot = (ty + ky)*34 + mx*16 + rowA + kx;
                    uint32_t af[4];
                    ldsm_x4(af, sb + foff + sw128((uint32_t)(slot*128 + kt*32 + chA*16)));
#pragma unroll
                    for (int nt = 0; nt < 4; nt++)
                        mma_fp16(acc[half][mx][nt], af, bf[nt]);
                }
            }
        }
    }

    // epilogue: relu -> fp16 pixel-major
#pragma unroll
    for (int half = 0; half < 2; half++){
        int gy = y0 + half*8 + tyw;
#pragma unroll
        for (int mx = 0; mx < 2; mx++){
            int px = x0 + mx*16 + (lane>>2);
            size_t base0 = ((size_t)gy*WL + px)*64;
            size_t base1 = ((size_t)gy*WL + px + 8)*64;
#pragma unroll
            for (int nt = 0; nt < 4; nt++){
                int co = (nthalf*4 + nt)*8 + (lane&3)*2;
                __half2 u0 = __floats2half2_rn(fmaxf(acc[half][mx][nt][0],0.f), fmaxf(acc[half][mx][nt][1],0.f));
                __half2 u1 = __floats2half2_rn(fmaxf(acc[half][mx][nt][2],0.f), fmaxf(acc[half][mx][nt][3],0.f));
                *(uint32_t*)(dsth + base0 + co) = *(uint32_t*)&u0;
                *(uint32_t*)(dsth + base1 + co) = *(uint32_t*)&u1;
            }
        }
    }
}

__global__ __launch_bounds__(C2_THR) void k_conv2(const float* __restrict__ w2){
    extern __shared__ __align__(1024) char sm[];
    uint32_t sb = smem_u32(sm);
    int tid = threadIdx.x, wid = tid>>5, lane = tid&31;

    for (int lin = tid; lin < 64*64*9; lin += C2_THR){
        float v = w2[lin];
        int co = lin / 576;
        int rem = lin - co*576;
        int ci = rem / 9;
        int k  = rem - ci*9;
        __half hv = __float2half_rn(v);
        *(__half*)(sm + C2_WS + k*8192 + sw128((uint32_t)(co*128 + ci*2))) = hv;
    }

    int n = 0;
    int tiles[3];
    for (int tt = blockIdx.x; tt < C2_TILES; tt += C2_GRID) tiles[n++] = tt;
    if (n == 0) return;

    const uint32_t foff[2] = {C2_F0, C2_F1};

    c2_stage(sb, foff[0], tiles[0], tid);
    CP_COMMIT();

    for (int k = 0; k < n; k++){
        if (k + 1 < n){
            c2_stage(sb, foff[(k+1)&1], tiles[k+1], tid);
            CP_COMMIT();
            CP_WAIT(1);
        } else {
            CP_WAIT(0);
        }
        __syncthreads();
        c2_compute(sb, foff[k&1], tiles[k], wid, lane);
        __syncthreads();
    }
}

// ================= segment counting sort ====================================
__global__ __launch_bounds__(256) void k_hist(const int* __restrict__ seg){
    __shared__ int hist[SS];
    int tid = threadIdx.x;
    hist[tid] = 0;
    __syncthreads();
    int b = blockIdx.y;
    int base = blockIdx.x * 1024;
#pragma unroll
    for (int i = 0; i < 4; i++){
        int s = seg[(size_t)b*HW + base + i*256 + tid];
        atomicAdd(&hist[s], 1);
    }
    __syncthreads();
    atomicAdd(&g_cnt[b*SS + tid], hist[tid]);
}

__global__ void k_scan(){
    __shared__ int s[1024];
    int t = threadIdx.x;
    int v = g_cnt[t];
    s[t] = v;
    __syncthreads();
    for (int d = 1; d < 1024; d <<= 1){
        int add = (t >= d) ? s[t-d] : 0;
        __syncthreads();
        s[t] += add;
        __syncthreads();
    }
    g_off[t] = s[t] - v;
}

__global__ __launch_bounds__(256) void k_scatter(const int* __restrict__ seg){
    int b = blockIdx.y;
    int p = blockIdx.x*256 + threadIdx.x;
    int sgm = seg[(size_t)b*HW + p];
    int bin = b*SS + sgm;
    int idx = atomicAdd(&g_cur[bin], 1);
    g_order[g_off[bin] + idx] = p;
}

// ================= conv3+pool: af-resident, 256-px tiles, cross-bin pipe ====
#define W_OFF 0
#define F3_0  98304
#define F3_1  131072
#define C3_SMEM 163840
#define C3_GRID 148
#define C3_TPX 256

__device__ __forceinline__ void c3_stage(uint32_t sb, uint32_t foff,
                                         const __half* featb, int off,
                                         int tbase, int npix, int nrows, int tid){
    for (int lin = tid; lin < nrows*8; lin += 256){
        int r = lin >> 3, part = lin & 7;
        int idx = tbase + r;
        bool v = idx < npix;
        const void* s;
        if (v){
            int pix = g_order[off + idx];
            s = (const void*)(featb + (size_t)pix*64 + part*8);
        } else s = (const void*)featb;
        cp_async16(sb + foff + sw128((uint32_t)(r*128 + part*16)), s, v);
    }
}

__global__ __launch_bounds__(256, 1) void k_conv3pool(const float* __restrict__ w3,
                                                      float* __restrict__ out){
    extern __shared__ __align__(1024) char sm[];
    int tid  = threadIdx.x;
    int wid  = tid >> 5;
    int lane = tid & 31;
    uint32_t sbase = smem_u32(sm);

    // ---- stage W once ----
#pragma unroll
    for (int rr = 0; rr < 3; rr++){
        int e = tid + rr*256;
        const float4* wrow = (const float4*)(w3 + (size_t)e*64);
#pragma unroll
        for (int k = 0; k < 16; k++){
            float4 f4 = wrow[k];
            __half2 h0 = __float22half2_rn(make_float2(f4.x, f4.y));
            __half2 h1 = __float22half2_rn(make_float2(f4.z, f4.w));
            uint2 u; u.x = *(uint32_t*)&h0; u.y = *(uint32_t*)&h1;
            *(uint2*)(sm + W_OFF + sw128((uint32_t)(e*128 + k*8))) = u;
        }
    }
    __syncthreads();

    // ---- weight fragments resident in registers ----
    int rowA = lane & 15, chA = lane >> 4;
    uint32_t af[6][4][4];
#pragma unroll
    for (int i = 0; i < 6; i++){
        int e0 = (wid*6 + i)*16;
#pragma unroll
        for (int kt = 0; kt < 4; kt++)
            ldsm_x4(af[i][kt], sbase + W_OFF + sw128((uint32_t)((e0 + rowA)*128 + kt*32 + chA*16)));
    }

    int rowB = lane & 7, chB = (lane >> 3) & 1, grpB = lane >> 4;
    const uint32_t foff[2] = {F3_0, F3_1};

    int mybins[7]; int nb = 0;
    for (int bin = blockIdx.x; bin < BB*SS; bin += C3_GRID) mybins[nb++] = bin;

    // prologue: stage tile 0 of bin 0
    {
        int bin = mybins[0];
        int npix = g_cnt[bin], off = g_off[bin];
        const __half* fb = g_h2 + (size_t)(bin >> 8)*HW*64;
        int rem0 = npix > C3_TPX ? C3_TPX : (npix < 0 ? 0 : npix);
        int nr0 = ((rem0 + 31) >> 5) * 32;
        c3_stage(sbase, foff[0], fb, off, 0, npix, nr0, tid);
    }
    CP_COMMIT();
    int pbuf = 0;

#pragma unroll 1
    for (int bi = 0; bi < nb; bi++){
        int bin  = mybins[bi];
        int npix = g_cnt[bin];
        int off  = g_off[bin];
        int ntiles = (npix + C3_TPX-1) / C3_TPX; if (ntiles < 1) ntiles = 1;

        float acc[6][2];
#pragma unroll
        for (int i = 0; i < 6; i++){ acc[i][0] = 0.f; acc[i][1] = 0.f; }

        for (int t = 0; t < ntiles; t++){
            int rem = npix - t*C3_TPX;
            if (rem > C3_TPX) rem = C3_TPX;
            if (rem < 0) rem = 0;
            int ntcN = (rem + 31) >> 5;

            bool has_next = false; int nbin = 0, ntb = 0;
            if (t + 1 < ntiles){ nbin = bin; ntb = t + 1; has_next = true; }
            else if (bi + 1 < nb){ nbin = mybins[bi+1]; ntb = 0; has_next = true; }
            if (has_next){
                int nnp = g_cnt[nbin], noff = g_off[nbin];
                const __half* nfb = g_h2 + (size_t)(nbin >> 8)*HW*64;
                int nrem = nnp - ntb*C3_TPX;
                if (nrem > C3_TPX) nrem = C3_TPX;
                if (nrem < 0) nrem = 0;
                int nr = ((nrem + 31) >> 5) * 32;
                c3_stage(sbase, foff[pbuf^1], nfb, noff, ntb*C3_TPX, nnp, nr, tid);
                CP_COMMIT();
                CP_WAIT(1);
            } else {
                CP_WAIT(0);
            }
            __syncthreads();
            uint32_t fbp = sbase + foff[pbuf];

#pragma unroll 1
            for (int ntc = 0; ntc < ntcN; ntc++){
                uint32_t bf[4][4][2];
#pragma unroll
                for (int kt = 0; kt < 4; kt++)
#pragma unroll
                for (int jp = 0; jp < 2; jp++){
                    uint32_t r[4];
                    int px = (ntc*4 + jp*2 + grpB)*8 + rowB;
                    ldsm_x4(r, fbp + sw128((uint32_t)(px*128 + kt*32 + chB*16)));
                    bf[jp*2][kt][0]   = r[0]; bf[jp*2][kt][1]   = r[1];
                    bf[jp*2+1][kt][0] = r[2]; bf[jp*2+1][kt][1] = r[3];
                }
#pragma unroll
                for (int i = 0; i < 6; i++){
                    float d[4][4];
#pragma unroll
                    for (int j = 0; j < 4; j++)
#pragma unroll
                    for (int q = 0; q < 4; q++) d[j][q] = 0.f;
#pragma unroll
                    for (int kt = 0; kt < 4; kt++)
#pragma unroll
                    for (int j = 0; j < 4; j++)
                        mma_fp16(d[j], af[i][kt], bf[j][kt]);
#pragma unroll
                    for (int j = 0; j < 4; j++){
                        acc[i][0] += fmaxf(d[j][0], 0.f) + fmaxf(d[j][1], 0.f);
                        acc[i][1] += fmaxf(d[j][2], 0.f) + fmaxf(d[j][3], 0.f);
                    }
                }
            }
            __syncthreads();
            pbuf ^= 1;
        }

        float inv = 1.f / (float)max(npix, 1);
#pragma unroll
        for (int i = 0; i < 6; i++){
            acc[i][0] += __shfl_xor_sync(0xffffffffu, acc[i][0], 1);
            acc[i][0] += __shfl_xor_sync(0xffffffffu, acc[i][0], 2);
            acc[i][1] += __shfl_xor_sync(0xffffffffu, acc[i][1], 1);
            acc[i][1] += __shfl_xor_sync(0xffffffffu, acc[i][1], 2);
        }
        if ((lane & 3) == 0){
            int row = lane >> 2;
            float* ob = out + (size_t)bin*EE;
#pragma unroll
            for (int i = 0; i < 6; i++){
                int e = (wid*6 + i)*16 + row;
                ob[e]     = acc[i][0] * inv;
                ob[e + 8] = acc[i][1] * inv;
            }
        }
    }
}

// ================= positional MLP: 128 CTAs =================================
#define POS_ROWS 32
__global__ __launch_bounds__(192) void k_pos(const float* __restrict__ cent,
        const float* __restrict__ w1, const float* __restrict__ b1,
        const float* __restrict__ w2, const float* __restrict__ b2,
        float* __restrict__ out){
    __shared__ __align__(16) float h2[384*POS_ROWS];
    int tid = threadIdx.x;
    int eq  = blockIdx.x;
    int rb  = blockIdx.y * POS_ROWS;
    for (int lin = tid; lin < 384*POS_ROWS; lin += 192){
        int j = lin >> 5, r = lin & 31;
        int rid = rb + r;
        float c0 = cent[rid*2+0] * (1.f/223.f);
        float c1 = cent[rid*2+1] * (1.f/223.f);
        h2[j*POS_ROWS + r] = fmaxf(fmaf(c0, w1[j], fmaf(c1, w1[384+j], b1[j])), 0.f);
    }
    __syncthreads();
    int e = eq*192 + tid;
    ull acc[16];
#pragma unroll
    for (int q = 0; q < 16; q++) acc[q] = 0ULL;
    for (int j = 0; j < 384; j++){
        float wv = w2[(size_t)j*768 + e];
        ull wp = pack2(wv, wv);
        const ull* hp = (const ull*)&h2[j*POS_ROWS];
#pragma unroll
        for (int q = 0; q < 16; q++) ffma2(acc[q], hp[q], wp);
    }
    float bv = b2[e];
#pragma unroll
    for (int q = 0; q < 16; q++){
        float2 v = unpack2(acc[q]);
        int rid = rb + 2*q;
        out[(size_t)rid*768 + e]     = v.x + bv;
        out[(size_t)(rid+1)*768 + e] = v.y + bv;
    }
}

// ================= launcher (two-stream fork/join inside graph capture) =====
extern "C" void kernel_launch(void* const* d_in, const int* in_sizes, int n_in,
                              void* d_out, int out_size){
    const float* img  = (const float*)d_in[0];
    const int*   seg  = (const int*)d_in[1];
    const float* cent = (const float*)d_in[2];
    const float* w1   = (const float*)d_in[3];
    const float* w2   = (const float*)d_in[4];
    const float* w3   = (const float*)d_in[5];
    const float* pw1  = (const float*)d_in[6];
    const float* pb1  = (const float*)d_in[7];
    const float* pw2  = (const float*)d_in[8];
    const float* pb2  = (const float*)d_in[9];
    float* out = (float*)d_out;

    static cudaStream_t sB = nullptr;
    static cudaEvent_t  e0 = nullptr, e1 = nullptr;
    if (!sB){
        cudaStreamCreateWithFlags(&sB, cudaStreamNonBlocking);
        cudaEventCreateWithFlags(&e0, cudaEventDisableTiming);
        cudaEventCreateWithFlags(&e1, cudaEventDisableTiming);
    }

    cudaFuncSetAttribute(k_conv2,
                         cudaFuncAttributeMaxDynamicSharedMemorySize, C2_SMEM);
    cudaFuncSetAttribute(k_conv3pool,
                         cudaFuncAttributeMaxDynamicSharedMemorySize, C3_SMEM);

    // fork: stream B handles segment sort + positional MLP
    cudaEventRecord(e0, 0);
    cudaStreamWaitEvent(sB, e0, 0);

    // stream 0: conv chain
    k_conv1<<<dim3(196,4), 256>>>(img, w1);
    k_conv2<<<C2_GRID, C2_THR, C2_SMEM>>>(w2);

    // stream B: sort chain + pos (independent of conv)
    k_zero<<<1, 1024, 0, sB>>>();
    k_hist<<<dim3(49,4), 256, 0, sB>>>(seg);
    k_scan<<<1, 1024, 0, sB>>>();
    k_scatter<<<dim3(196,4), 256, 0, sB>>>(seg);
    k_pos<<<dim3(4,32), 192, 0, sB>>>(cent, pw1, pb1, pw2, pb2, out + (size_t)BB*SS*EE);
    cudaEventRecord(e1, sB);

    // join: conv3pool needs conv2 (stream order) + sort results (event)
    cudaStreamWaitEvent(0, e1, 0);
    k_conv3pool<<<C3_GRID, 256, C3_SMEM>>>(w3, out);
}